// round 3
// baseline (speedup 1.0000x reference)
#include <cuda_runtime.h>
#include <cstdint>
#include <cstddef>

// ---------------- problem dims (fixed) ----------------
#define NTOK 8192            // 4*2048 tokens
#define HDIM 1024
#define DDIM 4096
#define KDIM 9216            // HDIM * 9 (silu + 8 spline bases)

// ---------------- GEMM tiling ----------------
#define TILE_M 128
#define TILE_N 256
#define KCHUNK 32            // tf32 elems per k-iter = 128 bytes per row
#define STAGES 4
#define NIT (KDIM / KCHUNK)  // 288
#define GTHREADS 512         // 16 warps: 2 (M) x 8 (N), warp tile 64x32
#define MT (NTOK / TILE_M)   // 64
#define NT (DDIM / TILE_N)   // 16

#define A_STAGE_BYTES (TILE_M * 128)   // 16384
#define B_STAGE_BYTES (TILE_N * 128)   // 32768
#define STAGE_BYTES (A_STAGE_BYTES + B_STAGE_BYTES)
#define DYN_SMEM (STAGES * STAGE_BYTES + 1024)

// ---------------- scratch (allocation-free: __device__ globals) ----------------
__device__ float g_act[(size_t)NTOK * KDIM];   // 302 MB tf32 features
__device__ float g_w[(size_t)DDIM * KDIM];     // 151 MB tf32 fused weights

// ---------------- helpers ----------------
__device__ __forceinline__ float to_tf32(float v) {
    uint32_t u;
    asm("cvt.rna.tf32.f32 %0, %1;" : "=r"(u) : "f"(v));
    return __uint_as_float(u);
}

__device__ __forceinline__ void cp_async16(uint32_t dst, const void* src) {
    asm volatile("cp.async.cg.shared.global [%0], [%1], 16;"
                 :: "r"(dst), "l"(src) : "memory");
}

__device__ __forceinline__ float gelu_exact(float v) {
    return 0.5f * v * (1.0f + erff(v * 0.70710678118654752f));
}

// knot value: matches numpy float32 arange(i-3)*0.4f + (-1.0f)
__device__ __forceinline__ float knot(int t) {
    return __fadd_rn(__fmul_rn(0.4f, (float)(t - 3)), -1.0f);
}

// physical shared address of logical (row, col-float) under SW128 XOR swizzle
__device__ __forceinline__ uint32_t swz_addr(uint32_t base, int row, int col) {
    return base + (uint32_t)row * 128u + (uint32_t)((col ^ ((row & 7) << 2)) << 2);
}

__device__ __forceinline__ uint32_t lds32(uint32_t addr) {
    uint32_t v;
    asm volatile("ld.shared.b32 %0, [%1];" : "=r"(v) : "r"(addr));
    return v;
}

__device__ __forceinline__ void mma_m16n8k8(float* c, const uint32_t* a, const uint32_t* b) {
    asm volatile(
        "mma.sync.aligned.m16n8k8.row.col.f32.tf32.tf32.f32 "
        "{%0,%1,%2,%3}, {%4,%5,%6,%7}, {%8,%9}, {%0,%1,%2,%3};"
        : "+f"(c[0]), "+f"(c[1]), "+f"(c[2]), "+f"(c[3])
        : "r"(a[0]), "r"(a[1]), "r"(a[2]), "r"(a[3]), "r"(b[0]), "r"(b[1]));
}

// ---------------- prep kernel 1: features -> g_act ----------------
__global__ void __launch_bounds__(256) prep_act_kernel(const float* __restrict__ x) {
    int idx = blockIdx.x * 256 + threadIdx.x;   // exactly NTOK*HDIM threads
    float xv = x[idx];
    float sig = 1.0f / (1.0f + expf(-xv));
    float silu = xv * sig;

    float b[11];
#pragma unroll
    for (int t = 0; t < 11; t++)
        b[t] = (xv >= knot(t) && xv < knot(t + 1)) ? 1.0f : 0.0f;
#pragma unroll
    for (int k = 1; k <= 3; k++) {
#pragma unroll
        for (int t = 0; t + k < 11; t++) {
            float gt = knot(t), gtk = knot(t + k);
            float gt1 = knot(t + 1), gtk1 = knot(t + k + 1);
            float left = (xv - gt) / (gtk - gt);
            float right = (gtk1 - xv) / (gtk1 - gt1);
            b[t] = left * b[t] + right * b[t + 1];
        }
    }

    int n = idx >> 10;
    int h = idx & 1023;
    float* dst = g_act + (size_t)n * KDIM + (size_t)h * 9;
    dst[0] = to_tf32(silu);
#pragma unroll
    for (int j = 0; j < 8; j++) dst[1 + j] = to_tf32(b[j]);
}

// ---------------- prep kernel 2: fused weights -> g_w ----------------
__global__ void __launch_bounds__(256) prep_w_kernel(const float* __restrict__ bw,
                                                     const float* __restrict__ sw,
                                                     const float* __restrict__ ss) {
    int idx = blockIdx.x * 256 + threadIdx.x;   // DDIM*HDIM threads
    float base = bw[idx];
    float scal = ss[idx];
    int d = idx >> 10;
    int h = idx & 1023;
    const float* swp = sw + (size_t)idx * 8;
    float* dst = g_w + (size_t)d * KDIM + (size_t)h * 9;
    dst[0] = to_tf32(base);
#pragma unroll
    for (int j = 0; j < 8; j++) dst[1 + j] = to_tf32(swp[j] * scal);
}

// ---------------- GEMM: issue cp.async for k-iter `it` ----------------
__device__ __forceinline__ void issue_loads(uint32_t smem_base,
                                            const char* a_gbase, const char* b_gbase,
                                            int it, int tid) {
    const int s = it & (STAGES - 1);
    uint32_t a_s = smem_base + (uint32_t)s * STAGE_BYTES;
    uint32_t b_s = a_s + A_STAGE_BYTES;
    const char* a_g = a_gbase + (size_t)it * (KCHUNK * 4);
    const char* b_g = b_gbase + (size_t)it * (KCHUNK * 4);

    // A tile: 128 rows x 128B = 1024 x 16B  (2 per thread)
#pragma unroll
    for (int i = 0; i < 2; i++) {
        int c = tid + i * GTHREADS;
        int row = c >> 3, c8 = c & 7;
        uint32_t off = ((uint32_t)row << 7) | ((uint32_t)c8 << 4);
        uint32_t swz = off ^ ((off >> 3) & 0x70u);
        cp_async16(a_s + swz, a_g + (size_t)row * (KDIM * 4) + ((size_t)c8 << 4));
    }
    // B tile: 256 rows x 128B = 2048 x 16B  (4 per thread)
#pragma unroll
    for (int i = 0; i < 4; i++) {
        int c = tid + i * GTHREADS;
        int row = c >> 3, c8 = c & 7;
        uint32_t off = ((uint32_t)row << 7) | ((uint32_t)c8 << 4);
        uint32_t swz = off ^ ((off >> 3) & 0x70u);
        cp_async16(b_s + swz, b_g + (size_t)row * (KDIM * 4) + ((size_t)c8 << 4));
    }
}

// ---------------- GEMM kernel ----------------
__global__ void __launch_bounds__(GTHREADS, 1) gemm_kernel(float* __restrict__ out) {
    extern __shared__ char dsmem[];

    const int tid = threadIdx.x;
    const int wid = tid >> 5;
    const int lane = tid & 31;
    const int lane4 = lane >> 2;   // groupID 0..7
    const int lanem = lane & 3;    // threadID-in-group 0..3
    const int warp_m = wid & 1;    // 0..1  (64-row slabs)
    const int warp_n = wid >> 1;   // 0..7  (32-col slabs)

    const int mt = blockIdx.x % MT;
    const int nt = blockIdx.x / MT;

    uint32_t smem_raw = (uint32_t)__cvta_generic_to_shared(dsmem);
    uint32_t smem_base = (smem_raw + 1023u) & ~1023u;

    const char* a_gbase = (const char*)(g_act + (size_t)mt * TILE_M * KDIM);
    const char* b_gbase = (const char*)(g_w + (size_t)nt * TILE_N * KDIM);

    float acc[4][4][4];
#pragma unroll
    for (int mi = 0; mi < 4; mi++)
#pragma unroll
        for (int ni = 0; ni < 4; ni++)
#pragma unroll
            for (int j = 0; j < 4; j++) acc[mi][ni][j] = 0.0f;

    // prologue: fill STAGES-1 stages
#pragma unroll
    for (int it = 0; it < STAGES - 1; it++) {
        issue_loads(smem_base, a_gbase, b_gbase, it, tid);
        asm volatile("cp.async.commit_group;" ::: "memory");
    }

    const int a_row0 = warp_m * 64 + lane4;   // + mi*16 (+8)
    const int b_row0 = warp_n * 32 + lane4;   // + ni*8

    for (int it = 0; it < NIT; it++) {
        asm volatile("cp.async.wait_group 2;" ::: "memory");
        __syncthreads();

        // issue next stage first (overlaps with compute below)
        const int nx = it + STAGES - 1;
        if (nx < NIT) issue_loads(smem_base, a_gbase, b_gbase, nx, tid);
        asm volatile("cp.async.commit_group;" ::: "memory");

        const int s = it & (STAGES - 1);
        const uint32_t a_base = smem_base + (uint32_t)s * STAGE_BYTES;
        const uint32_t b_base = a_base + A_STAGE_BYTES;

#pragma unroll
        for (int ks = 0; ks < 4; ks++) {
            const int kb = ks * 8;
            uint32_t afr[4][4];
            uint32_t bfr[4][2];
#pragma unroll
            for (int mi = 0; mi < 4; mi++) {
                int r0 = a_row0 + mi * 16;
                afr[mi][0] = lds32(swz_addr(a_base, r0,     kb + lanem));
                afr[mi][1] = lds32(swz_addr(a_base, r0 + 8, kb + lanem));
                afr[mi][2] = lds32(swz_addr(a_base, r0,     kb + lanem + 4));
                afr[mi][3] = lds32(swz_addr(a_base, r0 + 8, kb + lanem + 4));
            }
#pragma unroll
            for (int ni = 0; ni < 4; ni++) {
                int nr = b_row0 + ni * 8;
                bfr[ni][0] = lds32(swz_addr(b_base, nr, kb + lanem));
                bfr[ni][1] = lds32(swz_addr(b_base, nr, kb + lanem + 4));
            }
#pragma unroll
            for (int mi = 0; mi < 4; mi++)
#pragma unroll
                for (int ni = 0; ni < 4; ni++)
                    mma_m16n8k8(acc[mi][ni], afr[mi], bfr[ni]);
        }
    }

    asm volatile("cp.async.wait_group 0;" ::: "memory");

    // epilogue: GELU + direct float2 stores
    const int grow0 = mt * TILE_M + warp_m * 64 + lane4;
    const int gcol0 = nt * TILE_N + warp_n * 32 + 2 * lanem;
#pragma unroll
    for (int mi = 0; mi < 4; mi++) {
#pragma unroll
        for (int ni = 0; ni < 4; ni++) {
            int r = grow0 + mi * 16;
            int c = gcol0 + ni * 8;
            float2 v0, v1;
            v0.x = gelu_exact(acc[mi][ni][0]);
            v0.y = gelu_exact(acc[mi][ni][1]);
            v1.x = gelu_exact(acc[mi][ni][2]);
            v1.y = gelu_exact(acc[mi][ni][3]);
            *reinterpret_cast<float2*>(out + (size_t)r * DDIM + c) = v0;
            *reinterpret_cast<float2*>(out + (size_t)(r + 8) * DDIM + c) = v1;
        }
    }
}

// ---------------- launch ----------------
extern "C" void kernel_launch(void* const* d_in, const int* in_sizes, int n_in,
                              void* d_out, int out_size) {
    const float* x  = (const float*)d_in[0];
    const float* bw = (const float*)d_in[1];
    const float* sw = (const float*)d_in[2];
    const float* ss = (const float*)d_in[3];
    float* out = (float*)d_out;

    cudaFuncSetAttribute(gemm_kernel, cudaFuncAttributeMaxDynamicSharedMemorySize, DYN_SMEM);

    prep_act_kernel<<<(NTOK * HDIM) / 256, 256>>>(x);
    prep_w_kernel<<<(DDIM * HDIM) / 256, 256>>>(bw, sw, ss);
    gemm_kernel<<<MT * NT, GTHREADS, DYN_SMEM>>>(out);
}

// round 4
// speedup vs baseline: 2.0674x; 2.0674x over previous
#include <cuda_runtime.h>
#include <cuda_fp16.h>
#include <cstdint>
#include <cstddef>

// ---------------- problem dims (fixed) ----------------
#define NTOK 8192            // 4*2048 tokens
#define HDIM 1024
#define DDIM 4096
#define KDIM 9216            // HDIM * 9 (silu block [0,1024) + bases block [1024,9216))

// ---------------- GEMM tiling ----------------
#define TILE_M 128
#define TILE_N 256
#define KCHUNK 64            // fp16 elems per k-iter = 128 bytes per row
#define STAGES 4
#define NIT (KDIM / KCHUNK)  // 144
#define GTHREADS 512         // 16 warps: 2 (M) x 8 (N), warp tile 64x32
#define MT (NTOK / TILE_M)   // 64
#define NT (DDIM / TILE_N)   // 16

#define A_STAGE_BYTES (TILE_M * 128)   // 16384
#define B_STAGE_BYTES (TILE_N * 128)   // 32768
#define STAGE_BYTES (A_STAGE_BYTES + B_STAGE_BYTES)
#define DYN_SMEM (STAGES * STAGE_BYTES + 1024)

// ---------------- scratch (allocation-free: __device__ globals) ----------------
__device__ __half g_act[(size_t)NTOK * KDIM];   // 151 MB fp16 features
__device__ __half g_w[(size_t)DDIM * KDIM];     // 75.5 MB fp16 fused weights

// ---------------- helpers ----------------
__device__ __forceinline__ void cp_async16(uint32_t dst, const void* src) {
    asm volatile("cp.async.cg.shared.global [%0], [%1], 16;"
                 :: "r"(dst), "l"(src) : "memory");
}

__device__ __forceinline__ float gelu_exact(float v) {
    return 0.5f * v * (1.0f + erff(v * 0.70710678118654752f));
}

// knot value: matches numpy float32 arange(i-3)*0.4f + (-1.0f) — all constant-folded
__device__ __forceinline__ float knot(int t) {
    return __fadd_rn(__fmul_rn(0.4f, (float)(t - 3)), -1.0f);
}

// physical shared address of logical (row, b32col) under SW128 XOR swizzle
__device__ __forceinline__ uint32_t swz_addr(uint32_t base, int row, int col) {
    return base + (uint32_t)row * 128u + (uint32_t)((col ^ ((row & 7) << 2)) << 2);
}

__device__ __forceinline__ uint32_t lds32(uint32_t addr) {
    uint32_t v;
    asm volatile("ld.shared.b32 %0, [%1];" : "=r"(v) : "r"(addr));
    return v;
}

__device__ __forceinline__ void mma_m16n8k16(float* c, const uint32_t* a, const uint32_t* b) {
    asm volatile(
        "mma.sync.aligned.m16n8k16.row.col.f32.f16.f16.f32 "
        "{%0,%1,%2,%3}, {%4,%5,%6,%7}, {%8,%9}, {%0,%1,%2,%3};"
        : "+f"(c[0]), "+f"(c[1]), "+f"(c[2]), "+f"(c[3])
        : "r"(a[0]), "r"(a[1]), "r"(a[2]), "r"(a[3]), "r"(b[0]), "r"(b[1]));
}

// pack 8 floats -> uint4 of fp16
__device__ __forceinline__ uint4 pack8_h(const float* v) {
    union { __half2 h2[4]; uint4 u; } u;
    u.h2[0] = __floats2half2_rn(v[0], v[1]);
    u.h2[1] = __floats2half2_rn(v[2], v[3]);
    u.h2[2] = __floats2half2_rn(v[4], v[5]);
    u.h2[3] = __floats2half2_rn(v[6], v[7]);
    return u.u;
}

// ---------------- prep kernel 1: features -> g_act ----------------
// layout: k = h -> silu(x);  k = 1024 + 8h + j -> basis_j
__global__ void __launch_bounds__(256) prep_act_kernel(const float* __restrict__ x) {
    int idx = blockIdx.x * 256 + threadIdx.x;   // exactly NTOK*HDIM threads
    float xv = x[idx];
    float sig = 1.0f / (1.0f + expf(-xv));
    float silu = xv * sig;

    float b[11];
#pragma unroll
    for (int t = 0; t < 11; t++)
        b[t] = (xv >= knot(t) && xv < knot(t + 1)) ? 1.0f : 0.0f;
#pragma unroll
    for (int k = 1; k <= 3; k++) {
#pragma unroll
        for (int t = 0; t + k < 11; t++) {
            // denominators are compile-time constants -> reciprocal multiplies
            float rl = 1.0f / (knot(t + k) - knot(t));
            float rr = 1.0f / (knot(t + k + 1) - knot(t + 1));
            float left = (xv - knot(t)) * rl;
            float right = (knot(t + k + 1) - xv) * rr;
            b[t] = left * b[t] + right * b[t + 1];
        }
    }

    int n = idx >> 10;
    int h = idx & 1023;
    size_t base = (size_t)n * KDIM;
    g_act[base + h] = __float2half_rn(silu);
    *reinterpret_cast<uint4*>(&g_act[base + 1024 + 8 * (size_t)h]) = pack8_h(b);
}

// ---------------- prep kernel 2: fused weights -> g_w ----------------
__global__ void __launch_bounds__(256) prep_w_kernel(const float* __restrict__ bw,
                                                     const float* __restrict__ sw,
                                                     const float* __restrict__ ss) {
    int idx = blockIdx.x * 256 + threadIdx.x;   // DDIM*HDIM threads
    float base = bw[idx];
    float scal = ss[idx];
    int d = idx >> 10;
    int h = idx & 1023;

    float w[8];
    const float4* swp = reinterpret_cast<const float4*>(sw + (size_t)idx * 8);
    float4 s0 = swp[0], s1 = swp[1];
    w[0] = s0.x * scal; w[1] = s0.y * scal; w[2] = s0.z * scal; w[3] = s0.w * scal;
    w[4] = s1.x * scal; w[5] = s1.y * scal; w[6] = s1.z * scal; w[7] = s1.w * scal;

    size_t dbase = (size_t)d * KDIM;
    g_w[dbase + h] = __float2half_rn(base);
    *reinterpret_cast<uint4*>(&g_w[dbase + 1024 + 8 * (size_t)h]) = pack8_h(w);
}

// ---------------- GEMM: issue cp.async for k-iter `it` ----------------
__device__ __forceinline__ void issue_loads(uint32_t smem_base,
                                            const char* a_gbase, const char* b_gbase,
                                            int it, int tid) {
    const int s = it & (STAGES - 1);
    uint32_t a_s = smem_base + (uint32_t)s * STAGE_BYTES;
    uint32_t b_s = a_s + A_STAGE_BYTES;
    const char* a_g = a_gbase + (size_t)it * 128;   // 64 halfs = 128 B per k-iter
    const char* b_g = b_gbase + (size_t)it * 128;

    // A tile: 128 rows x 128B = 1024 x 16B  (2 per thread)
#pragma unroll
    for (int i = 0; i < 2; i++) {
        int c = tid + i * GTHREADS;
        int row = c >> 3, c8 = c & 7;
        uint32_t off = ((uint32_t)row << 7) | ((uint32_t)c8 << 4);
        uint32_t swz = off ^ ((off >> 3) & 0x70u);
        cp_async16(a_s + swz, a_g + (size_t)row * (KDIM * 2) + ((size_t)c8 << 4));
    }
    // B tile: 256 rows x 128B = 2048 x 16B  (4 per thread)
#pragma unroll
    for (int i = 0; i < 4; i++) {
        int c = tid + i * GTHREADS;
        int row = c >> 3, c8 = c & 7;
        uint32_t off = ((uint32_t)row << 7) | ((uint32_t)c8 << 4);
        uint32_t swz = off ^ ((off >> 3) & 0x70u);
        cp_async16(b_s + swz, b_g + (size_t)row * (KDIM * 2) + ((size_t)c8 << 4));
    }
}

// ---------------- GEMM kernel ----------------
__global__ void __launch_bounds__(GTHREADS, 1) gemm_kernel(float* __restrict__ out) {
    extern __shared__ char dsmem[];

    const int tid = threadIdx.x;
    const int wid = tid >> 5;
    const int lane = tid & 31;
    const int lane4 = lane >> 2;   // groupID 0..7
    const int lanem = lane & 3;    // threadID-in-group 0..3
    const int warp_m = wid & 1;    // 0..1  (64-row slabs)
    const int warp_n = wid >> 1;   // 0..7  (32-col slabs)

    // grouped rasterization: 8 m-tiles x 16 n-tiles per group (128 CTAs)
    const int bid = blockIdx.x;
    const int mt = ((bid >> 7) << 3) | (bid & 7);
    const int nt = (bid >> 3) & 15;

    uint32_t smem_raw = (uint32_t)__cvta_generic_to_shared(dsmem);
    uint32_t smem_base = (smem_raw + 1023u) & ~1023u;

    const char* a_gbase = (const char*)(g_act + (size_t)mt * TILE_M * KDIM);
    const char* b_gbase = (const char*)(g_w + (size_t)nt * TILE_N * KDIM);

    float acc[4][4][4];
#pragma unroll
    for (int mi = 0; mi < 4; mi++)
#pragma unroll
        for (int ni = 0; ni < 4; ni++)
#pragma unroll
            for (int j = 0; j < 4; j++) acc[mi][ni][j] = 0.0f;

    // prologue: fill STAGES-1 stages
#pragma unroll
    for (int it = 0; it < STAGES - 1; it++) {
        issue_loads(smem_base, a_gbase, b_gbase, it, tid);
        asm volatile("cp.async.commit_group;" ::: "memory");
    }

    const int a_row0 = warp_m * 64 + lane4;   // + mi*16 (+8)
    const int b_row0 = warp_n * 32 + lane4;   // + ni*8

    for (int it = 0; it < NIT; it++) {
        asm volatile("cp.async.wait_group 2;" ::: "memory");
        __syncthreads();

        // issue next stage first (overlaps with compute below)
        const int nx = it + STAGES - 1;
        if (nx < NIT) issue_loads(smem_base, a_gbase, b_gbase, nx, tid);
        asm volatile("cp.async.commit_group;" ::: "memory");

        const int s = it & (STAGES - 1);
        const uint32_t a_base = smem_base + (uint32_t)s * STAGE_BYTES;
        const uint32_t b_base = a_base + A_STAGE_BYTES;

#pragma unroll
        for (int ks = 0; ks < 4; ks++) {
            const int kb = ks * 8;   // b32 column base within the 128B row
            uint32_t afr[4][4];
            uint32_t bfr[4][2];
#pragma unroll
            for (int mi = 0; mi < 4; mi++) {
                int r0 = a_row0 + mi * 16;
                afr[mi][0] = lds32(swz_addr(a_base, r0,     kb + lanem));
                afr[mi][1] = lds32(swz_addr(a_base, r0 + 8, kb + lanem));
                afr[mi][2] = lds32(swz_addr(a_base, r0,     kb + lanem + 4));
                afr[mi][3] = lds32(swz_addr(a_base, r0 + 8, kb + lanem + 4));
            }
#pragma unroll
            for (int ni = 0; ni < 4; ni++) {
                int nr = b_row0 + ni * 8;
                bfr[ni][0] = lds32(swz_addr(b_base, nr, kb + lanem));
                bfr[ni][1] = lds32(swz_addr(b_base, nr, kb + lanem + 4));
            }
#pragma unroll
            for (int mi = 0; mi < 4; mi++)
#pragma unroll
                for (int ni = 0; ni < 4; ni++)
                    mma_m16n8k16(acc[mi][ni], afr[mi], bfr[ni]);
        }
    }

    asm volatile("cp.async.wait_group 0;" ::: "memory");

    // epilogue: GELU + direct float2 stores
    const int grow0 = mt * TILE_M + warp_m * 64 + lane4;
    const int gcol0 = nt * TILE_N + warp_n * 32 + 2 * lanem;
#pragma unroll
    for (int mi = 0; mi < 4; mi++) {
#pragma unroll
        for (int ni = 0; ni < 4; ni++) {
            int r = grow0 + mi * 16;
            int c = gcol0 + ni * 8;
            float2 v0, v1;
            v0.x = gelu_exact(acc[mi][ni][0]);
            v0.y = gelu_exact(acc[mi][ni][1]);
            v1.x = gelu_exact(acc[mi][ni][2]);
            v1.y = gelu_exact(acc[mi][ni][3]);
            *reinterpret_cast<float2*>(out + (size_t)r * DDIM + c) = v0;
            *reinterpret_cast<float2*>(out + (size_t)(r + 8) * DDIM + c) = v1;
        }
    }
}

// ---------------- launch ----------------
extern "C" void kernel_launch(void* const* d_in, const int* in_sizes, int n_in,
                              void* d_out, int out_size) {
    const float* x  = (const float*)d_in[0];
    const float* bw = (const float*)d_in[1];
    const float* sw = (const float*)d_in[2];
    const float* ss = (const float*)d_in[3];
    float* out = (float*)d_out;

    cudaFuncSetAttribute(gemm_kernel, cudaFuncAttributeMaxDynamicSharedMemorySize, DYN_SMEM);

    prep_act_kernel<<<(NTOK * HDIM) / 256, 256>>>(x);
    prep_w_kernel<<<(DDIM * HDIM) / 256, 256>>>(bw, sw, ss);
    gemm_kernel<<<MT * NT, GTHREADS, DYN_SMEM>>>(out);
}

// round 5
// speedup vs baseline: 2.2280x; 1.0777x over previous
#include <cuda_runtime.h>
#include <cuda_fp16.h>
#include <cstdint>
#include <cstddef>

// ---------------- problem dims (fixed) ----------------
#define NTOK 8192            // 4*2048 tokens
#define HDIM 1024
#define DDIM 4096
#define KDIM 9216            // HDIM * 9 (silu block [0,1024) + bases block [1024,9216))

// ---------------- GEMM tiling ----------------
#define TILE_M 128
#define TILE_N 256
#define KCHUNK 64            // fp16 elems per k-iter = 128 bytes per row
#define STAGES 4
#define NIT (KDIM / KCHUNK)  // 144
#define GTHREADS 256         // 8 warps: 2 (M) x 4 (N), warp tile 64x64
#define MT (NTOK / TILE_M)   // 64
#define NT (DDIM / TILE_N)   // 16

#define A_STAGE_BYTES (TILE_M * 128)   // 16384
#define B_STAGE_BYTES (TILE_N * 128)   // 32768
#define STAGE_BYTES (A_STAGE_BYTES + B_STAGE_BYTES)
#define DYN_SMEM (STAGES * STAGE_BYTES + 1024)

// ---------------- scratch (allocation-free: __device__ globals) ----------------
__device__ __half g_act[(size_t)NTOK * KDIM];   // 151 MB fp16 features
__device__ __half g_w[(size_t)DDIM * KDIM];     // 75.5 MB fp16 fused weights

// ---------------- helpers ----------------
__device__ __forceinline__ void cp_async16(uint32_t dst, const void* src) {
    asm volatile("cp.async.cg.shared.global [%0], [%1], 16;"
                 :: "r"(dst), "l"(src) : "memory");
}

__device__ __forceinline__ float gelu_exact(float v) {
    return 0.5f * v * (1.0f + erff(v * 0.70710678118654752f));
}

// knot value: matches numpy float32 arange(i-3)*0.4f + (-1.0f) — constant-folded
__device__ __forceinline__ float knot(int t) {
    return __fadd_rn(__fmul_rn(0.4f, (float)(t - 3)), -1.0f);
}

// physical shared address of logical (row, b32col) under SW128 XOR swizzle
__device__ __forceinline__ uint32_t swz_addr(uint32_t base, int row, int col) {
    return base + (uint32_t)row * 128u + (uint32_t)((col ^ ((row & 7) << 2)) << 2);
}

__device__ __forceinline__ uint32_t lds32(uint32_t addr) {
    uint32_t v;
    asm volatile("ld.shared.b32 %0, [%1];" : "=r"(v) : "r"(addr));
    return v;
}

__device__ __forceinline__ void mma_m16n8k16(float* c, const uint32_t* a, const uint32_t* b) {
    asm volatile(
        "mma.sync.aligned.m16n8k16.row.col.f32.f16.f16.f32 "
        "{%0,%1,%2,%3}, {%4,%5,%6,%7}, {%8,%9}, {%0,%1,%2,%3};"
        : "+f"(c[0]), "+f"(c[1]), "+f"(c[2]), "+f"(c[3])
        : "r"(a[0]), "r"(a[1]), "r"(a[2]), "r"(a[3]), "r"(b[0]), "r"(b[1]));
}

// pack 8 floats -> uint4 of fp16
__device__ __forceinline__ uint4 pack8_h(const float* v) {
    union { __half2 h2[4]; uint4 u; } u;
    u.h2[0] = __floats2half2_rn(v[0], v[1]);
    u.h2[1] = __floats2half2_rn(v[2], v[3]);
    u.h2[2] = __floats2half2_rn(v[4], v[5]);
    u.h2[3] = __floats2half2_rn(v[6], v[7]);
    return u.u;
}

// ---------------- prep kernel 1: features -> g_act ----------------
// layout: k = h -> silu(x);  k = 1024 + 8h + j -> basis_j
__global__ void __launch_bounds__(256) prep_act_kernel(const float* __restrict__ x) {
    int idx = blockIdx.x * 256 + threadIdx.x;   // exactly NTOK*HDIM threads
    float xv = x[idx];
    float sig = 1.0f / (1.0f + expf(-xv));
    float silu = xv * sig;

    float b[11];
#pragma unroll
    for (int t = 0; t < 11; t++)
        b[t] = (xv >= knot(t) && xv < knot(t + 1)) ? 1.0f : 0.0f;
#pragma unroll
    for (int k = 1; k <= 3; k++) {
#pragma unroll
        for (int t = 0; t + k < 11; t++) {
            float rl = 1.0f / (knot(t + k) - knot(t));
            float rr = 1.0f / (knot(t + k + 1) - knot(t + 1));
            float left = (xv - knot(t)) * rl;
            float right = (knot(t + k + 1) - xv) * rr;
            b[t] = left * b[t] + right * b[t + 1];
        }
    }

    int n = idx >> 10;
    int h = idx & 1023;
    size_t base = (size_t)n * KDIM;
    g_act[base + h] = __float2half_rn(silu);
    *reinterpret_cast<uint4*>(&g_act[base + 1024 + 8 * (size_t)h]) = pack8_h(b);
}

// ---------------- prep kernel 2: fused weights -> g_w ----------------
__global__ void __launch_bounds__(256) prep_w_kernel(const float* __restrict__ bw,
                                                     const float* __restrict__ sw,
                                                     const float* __restrict__ ss) {
    int idx = blockIdx.x * 256 + threadIdx.x;   // DDIM*HDIM threads
    float base = bw[idx];
    float scal = ss[idx];
    int d = idx >> 10;
    int h = idx & 1023;

    float w[8];
    const float4* swp = reinterpret_cast<const float4*>(sw + (size_t)idx * 8);
    float4 s0 = swp[0], s1 = swp[1];
    w[0] = s0.x * scal; w[1] = s0.y * scal; w[2] = s0.z * scal; w[3] = s0.w * scal;
    w[4] = s1.x * scal; w[5] = s1.y * scal; w[6] = s1.z * scal; w[7] = s1.w * scal;

    size_t dbase = (size_t)d * KDIM;
    g_w[dbase + h] = __float2half_rn(base);
    *reinterpret_cast<uint4*>(&g_w[dbase + 1024 + 8 * (size_t)h]) = pack8_h(w);
}

// ---------------- GEMM: issue cp.async for k-iter `it` ----------------
__device__ __forceinline__ void issue_loads(uint32_t smem_base,
                                            const char* a_gbase, const char* b_gbase,
                                            int it, int tid) {
    const int s = it & (STAGES - 1);
    uint32_t a_s = smem_base + (uint32_t)s * STAGE_BYTES;
    uint32_t b_s = a_s + A_STAGE_BYTES;
    const char* a_g = a_gbase + (size_t)it * 128;   // 64 halfs = 128 B per k-iter
    const char* b_g = b_gbase + (size_t)it * 128;

    // A tile: 128 rows x 128B = 1024 x 16B  (4 per thread)
#pragma unroll
    for (int i = 0; i < 4; i++) {
        int c = tid + i * GTHREADS;
        int row = c >> 3, c8 = c & 7;
        uint32_t off = ((uint32_t)row << 7) | ((uint32_t)c8 << 4);
        uint32_t swz = off ^ ((off >> 3) & 0x70u);
        cp_async16(a_s + swz, a_g + (size_t)row * (KDIM * 2) + ((size_t)c8 << 4));
    }
    // B tile: 256 rows x 128B = 2048 x 16B  (8 per thread)
#pragma unroll
    for (int i = 0; i < 8; i++) {
        int c = tid + i * GTHREADS;
        int row = c >> 3, c8 = c & 7;
        uint32_t off = ((uint32_t)row << 7) | ((uint32_t)c8 << 4);
        uint32_t swz = off ^ ((off >> 3) & 0x70u);
        cp_async16(b_s + swz, b_g + (size_t)row * (KDIM * 2) + ((size_t)c8 << 4));
    }
}

// ---------------- GEMM kernel ----------------
__global__ void __launch_bounds__(GTHREADS, 1) gemm_kernel(float* __restrict__ out) {
    extern __shared__ char dsmem[];

    const int tid = threadIdx.x;
    const int wid = tid >> 5;
    const int lane = tid & 31;
    const int lane4 = lane >> 2;   // groupID 0..7
    const int lanem = lane & 3;    // threadID-in-group 0..3
    const int warp_m = wid & 1;    // 0..1  (64-row slabs)
    const int warp_n = wid >> 1;   // 0..3  (64-col slabs)

    // grouped rasterization: 8 m-tiles x 16 n-tiles per group (128 CTAs)
    const int bid = blockIdx.x;
    const int mt = ((bid >> 7) << 3) | (bid & 7);
    const int nt = (bid >> 3) & 15;

    uint32_t smem_raw = (uint32_t)__cvta_generic_to_shared(dsmem);
    uint32_t smem_base = (smem_raw + 1023u) & ~1023u;

    const char* a_gbase = (const char*)(g_act + (size_t)mt * TILE_M * KDIM);
    const char* b_gbase = (const char*)(g_w + (size_t)nt * TILE_N * KDIM);

    float acc[4][8][4];
#pragma unroll
    for (int mi = 0; mi < 4; mi++)
#pragma unroll
        for (int ni = 0; ni < 8; ni++)
#pragma unroll
            for (int j = 0; j < 4; j++) acc[mi][ni][j] = 0.0f;

    // prologue: fill STAGES-1 stages
#pragma unroll
    for (int it = 0; it < STAGES - 1; it++) {
        issue_loads(smem_base, a_gbase, b_gbase, it, tid);
        asm volatile("cp.async.commit_group;" ::: "memory");
    }

    const int a_row0 = warp_m * 64 + lane4;   // + mi*16 (+8)
    const int b_row0 = warp_n * 64 + lane4;   // + ni*8

    for (int it = 0; it < NIT; it++) {
        asm volatile("cp.async.wait_group 2;" ::: "memory");
        __syncthreads();

        // issue next stage first (overlaps with compute below)
        const int nx = it + STAGES - 1;
        if (nx < NIT) issue_loads(smem_base, a_gbase, b_gbase, nx, tid);
        asm volatile("cp.async.commit_group;" ::: "memory");

        const int s = it & (STAGES - 1);
        const uint32_t a_base = smem_base + (uint32_t)s * STAGE_BYTES;
        const uint32_t b_base = a_base + A_STAGE_BYTES;

#pragma unroll
        for (int ks = 0; ks < 4; ks++) {
            const int kb = ks * 8;   // b32 column base within the 128B row
            uint32_t afr[4][4];
            uint32_t bfr[8][2];
#pragma unroll
            for (int mi = 0; mi < 4; mi++) {
                int r0 = a_row0 + mi * 16;
                afr[mi][0] = lds32(swz_addr(a_base, r0,     kb + lanem));
                afr[mi][1] = lds32(swz_addr(a_base, r0 + 8, kb + lanem));
                afr[mi][2] = lds32(swz_addr(a_base, r0,     kb + lanem + 4));
                afr[mi][3] = lds32(swz_addr(a_base, r0 + 8, kb + lanem + 4));
            }
#pragma unroll
            for (int ni = 0; ni < 8; ni++) {
                int nr = b_row0 + ni * 8;
                bfr[ni][0] = lds32(swz_addr(b_base, nr, kb + lanem));
                bfr[ni][1] = lds32(swz_addr(b_base, nr, kb + lanem + 4));
            }
#pragma unroll
            for (int mi = 0; mi < 4; mi++)
#pragma unroll
                for (int ni = 0; ni < 8; ni++)
                    mma_m16n8k16(acc[mi][ni], afr[mi], bfr[ni]);
        }
    }

    asm volatile("cp.async.wait_group 0;" ::: "memory");

    // epilogue: GELU + direct float2 stores
    const int grow0 = mt * TILE_M + warp_m * 64 + lane4;
    const int gcol0 = nt * TILE_N + warp_n * 64 + 2 * lanem;
#pragma unroll
    for (int mi = 0; mi < 4; mi++) {
#pragma unroll
        for (int ni = 0; ni < 8; ni++) {
            int r = grow0 + mi * 16;
            int c = gcol0 + ni * 8;
            float2 v0, v1;
            v0.x = gelu_exact(acc[mi][ni][0]);
            v0.y = gelu_exact(acc[mi][ni][1]);
            v1.x = gelu_exact(acc[mi][ni][2]);
            v1.y = gelu_exact(acc[mi][ni][3]);
            *reinterpret_cast<float2*>(out + (size_t)r * DDIM + c) = v0;
            *reinterpret_cast<float2*>(out + (size_t)(r + 8) * DDIM + c) = v1;
        }
    }
}

// ---------------- launch ----------------
extern "C" void kernel_launch(void* const* d_in, const int* in_sizes, int n_in,
                              void* d_out, int out_size) {
    const float* x  = (const float*)d_in[0];
    const float* bw = (const float*)d_in[1];
    const float* sw = (const float*)d_in[2];
    const float* ss = (const float*)d_in[3];
    float* out = (float*)d_out;

    cudaFuncSetAttribute(gemm_kernel, cudaFuncAttributeMaxDynamicSharedMemorySize, DYN_SMEM);

    prep_act_kernel<<<(NTOK * HDIM) / 256, 256>>>(x);
    prep_w_kernel<<<(DDIM * HDIM) / 256, 256>>>(bw, sw, ss);
    gemm_kernel<<<MT * NT, GTHREADS, DYN_SMEM>>>(out);
}

// round 6
// speedup vs baseline: 2.2450x; 1.0076x over previous
#include <cuda_runtime.h>
#include <cuda_fp16.h>
#include <cstdint>
#include <cstddef>

// ---------------- problem dims (fixed) ----------------
#define NTOK 8192            // 4*2048 tokens
#define HDIM 1024
#define DDIM 4096
#define KDIM 9216            // HDIM * 9 (silu block [0,1024) + bases block [1024,9216))

// ---------------- GEMM tiling ----------------
#define TILE_M 128
#define TILE_N 256
#define KCHUNK 64            // fp16 elems per k-iter = 128 bytes per row
#define STAGES 4
#define NIT (KDIM / KCHUNK)  // 144
#define GTHREADS 256         // 8 warps: 2 (M) x 4 (N), warp tile 64x64
#define MT (NTOK / TILE_M)   // 64
#define NT (DDIM / TILE_N)   // 16

#define A_STAGE_BYTES (TILE_M * 128)   // 16384
#define B_STAGE_BYTES (TILE_N * 128)   // 32768
#define STAGE_BYTES (A_STAGE_BYTES + B_STAGE_BYTES)
#define DYN_SMEM (STAGES * STAGE_BYTES + 1024)

// ---------------- scratch (allocation-free: __device__ globals) ----------------
__device__ __half g_act[(size_t)NTOK * KDIM];   // 151 MB fp16 features
__device__ __half g_w[(size_t)DDIM * KDIM];     // 75.5 MB fp16 fused weights

// ---------------- helpers ----------------
__device__ __forceinline__ void cp_async16(uint32_t dst, const void* src) {
    asm volatile("cp.async.cg.shared.global [%0], [%1], 16;"
                 :: "r"(dst), "l"(src) : "memory");
}

__device__ __forceinline__ float gelu_exact(float v) {
    return 0.5f * v * (1.0f + erff(v * 0.70710678118654752f));
}

// knot value: matches numpy float32 arange(i-3)*0.4f + (-1.0f) — constant-folded
__device__ __forceinline__ float knot(int t) {
    return __fadd_rn(__fmul_rn(0.4f, (float)(t - 3)), -1.0f);
}

__device__ __forceinline__ void ldsm_x4(uint32_t* r, uint32_t addr) {
    asm volatile("ldmatrix.sync.aligned.m8n8.x4.shared.b16 {%0,%1,%2,%3}, [%4];"
                 : "=r"(r[0]), "=r"(r[1]), "=r"(r[2]), "=r"(r[3]) : "r"(addr));
}

__device__ __forceinline__ void mma_m16n8k16(float* c, const uint32_t* a, const uint32_t* b) {
    asm volatile(
        "mma.sync.aligned.m16n8k16.row.col.f32.f16.f16.f32 "
        "{%0,%1,%2,%3}, {%4,%5,%6,%7}, {%8,%9}, {%0,%1,%2,%3};"
        : "+f"(c[0]), "+f"(c[1]), "+f"(c[2]), "+f"(c[3])
        : "r"(a[0]), "r"(a[1]), "r"(a[2]), "r"(a[3]), "r"(b[0]), "r"(b[1]));
}

// pack 8 floats -> uint4 of fp16
__device__ __forceinline__ uint4 pack8_h(const float* v) {
    union { __half2 h2[4]; uint4 u; } u;
    u.h2[0] = __floats2half2_rn(v[0], v[1]);
    u.h2[1] = __floats2half2_rn(v[2], v[3]);
    u.h2[2] = __floats2half2_rn(v[4], v[5]);
    u.h2[3] = __floats2half2_rn(v[6], v[7]);
    return u.u;
}

// ---------------- prep kernel 1: features -> g_act ----------------
// layout: k = h -> silu(x);  k = 1024 + 8h + j -> basis_j
__global__ void __launch_bounds__(256) prep_act_kernel(const float* __restrict__ x) {
    int idx = blockIdx.x * 256 + threadIdx.x;   // exactly NTOK*HDIM threads
    float xv = x[idx];
    float sig = 1.0f / (1.0f + __expf(-xv));
    float silu = xv * sig;

    float b[11];
#pragma unroll
    for (int t = 0; t < 11; t++)
        b[t] = (xv >= knot(t) && xv < knot(t + 1)) ? 1.0f : 0.0f;
#pragma unroll
    for (int k = 1; k <= 3; k++) {
#pragma unroll
        for (int t = 0; t + k < 11; t++) {
            float rl = 1.0f / (knot(t + k) - knot(t));
            float rr = 1.0f / (knot(t + k + 1) - knot(t + 1));
            float left = (xv - knot(t)) * rl;
            float right = (knot(t + k + 1) - xv) * rr;
            b[t] = left * b[t] + right * b[t + 1];
        }
    }

    int n = idx >> 10;
    int h = idx & 1023;
    size_t base = (size_t)n * KDIM;
    g_act[base + h] = __float2half_rn(silu);
    *reinterpret_cast<uint4*>(&g_act[base + 1024 + 8 * (size_t)h]) = pack8_h(b);
}

// ---------------- prep kernel 2: fused weights -> g_w ----------------
__global__ void __launch_bounds__(256) prep_w_kernel(const float* __restrict__ bw,
                                                     const float* __restrict__ sw,
                                                     const float* __restrict__ ss) {
    int idx = blockIdx.x * 256 + threadIdx.x;   // DDIM*HDIM threads
    float base = bw[idx];
    float scal = ss[idx];
    int d = idx >> 10;
    int h = idx & 1023;

    float w[8];
    const float4* swp = reinterpret_cast<const float4*>(sw + (size_t)idx * 8);
    float4 s0 = swp[0], s1 = swp[1];
    w[0] = s0.x * scal; w[1] = s0.y * scal; w[2] = s0.z * scal; w[3] = s0.w * scal;
    w[4] = s1.x * scal; w[5] = s1.y * scal; w[6] = s1.z * scal; w[7] = s1.w * scal;

    size_t dbase = (size_t)d * KDIM;
    g_w[dbase + h] = __float2half_rn(base);
    *reinterpret_cast<uint4*>(&g_w[dbase + 1024 + 8 * (size_t)h]) = pack8_h(w);
}

// ---------------- GEMM: issue cp.async for k-iter `it` ----------------
__device__ __forceinline__ void issue_loads(uint32_t smem_base,
                                            const char* a_gbase, const char* b_gbase,
                                            int it, int tid) {
    const int s = it & (STAGES - 1);
    uint32_t a_s = smem_base + (uint32_t)s * STAGE_BYTES;
    uint32_t b_s = a_s + A_STAGE_BYTES;
    const char* a_g = a_gbase + (size_t)it * 128;   // 64 halfs = 128 B per k-iter
    const char* b_g = b_gbase + (size_t)it * 128;

    // A tile: 128 rows x 128B = 1024 x 16B  (4 per thread)
#pragma unroll
    for (int i = 0; i < 4; i++) {
        int c = tid + i * GTHREADS;
        int row = c >> 3, c8 = c & 7;
        uint32_t off = ((uint32_t)row << 7) | ((uint32_t)c8 << 4);
        uint32_t swz = off ^ ((off >> 3) & 0x70u);
        cp_async16(a_s + swz, a_g + (size_t)row * (KDIM * 2) + ((size_t)c8 << 4));
    }
    // B tile: 256 rows x 128B = 2048 x 16B  (8 per thread)
#pragma unroll
    for (int i = 0; i < 8; i++) {
        int c = tid + i * GTHREADS;
        int row = c >> 3, c8 = c & 7;
        uint32_t off = ((uint32_t)row << 7) | ((uint32_t)c8 << 4);
        uint32_t swz = off ^ ((off >> 3) & 0x70u);
        cp_async16(b_s + swz, b_g + (size_t)row * (KDIM * 2) + ((size_t)c8 << 4));
    }
}

// ---------------- GEMM kernel ----------------
__global__ void __launch_bounds__(GTHREADS, 1) gemm_kernel(float* __restrict__ out) {
    extern __shared__ char dsmem[];

    const int tid = threadIdx.x;
    const int wid = tid >> 5;
    const int lane = tid & 31;
    const int lane4 = lane >> 2;   // groupID 0..7
    const int lanem = lane & 3;    // threadID-in-group 0..3
    const int warp_m = wid & 1;    // 0..1  (64-row slabs)
    const int warp_n = wid >> 1;   // 0..3  (64-col slabs)

    // grouped rasterization: 8 m-tiles x 16 n-tiles per group (128 CTAs)
    const int bid = blockIdx.x;
    const int mt = ((bid >> 7) << 3) | (bid & 7);
    const int nt = (bid >> 3) & 15;

    uint32_t smem_raw = (uint32_t)__cvta_generic_to_shared(dsmem);
    uint32_t smem_base = (smem_raw + 1023u) & ~1023u;

    const char* a_gbase = (const char*)(g_act + (size_t)mt * TILE_M * KDIM);
    const char* b_gbase = (const char*)(g_w + (size_t)nt * TILE_N * KDIM);

    float acc[4][8][4];
#pragma unroll
    for (int mi = 0; mi < 4; mi++)
#pragma unroll
        for (int ni = 0; ni < 8; ni++)
#pragma unroll
            for (int j = 0; j < 4; j++) acc[mi][ni][j] = 0.0f;

    // prologue: fill STAGES-1 stages
#pragma unroll
    for (int it = 0; it < STAGES - 1; it++) {
        issue_loads(smem_base, a_gbase, b_gbase, it, tid);
        asm volatile("cp.async.commit_group;" ::: "memory");
    }

    // ldmatrix lane-address components
    const int xk = lane & 7;                     // swizzle XOR term (= row & 7)
    // A: row = warp_m*64 + (lane&15) + mi*16 ; c8 = 2*ks + (lane>>4)
    const int a_row_l = warp_m * 64 + (lane & 15);
    const int a_hi = lane >> 4;
    // B: row = warp_n*64 + p*16 + (quad>>1)*8 + (lane&7) ; c8 = 2*ks + (quad&1)
    const int quad = lane >> 3;
    const int b_row_l = warp_n * 64 + ((quad >> 1) << 3) + (lane & 7);
    const int b_lo = quad & 1;

    for (int it = 0; it < NIT; it++) {
        asm volatile("cp.async.wait_group 2;" ::: "memory");
        __syncthreads();

        // issue next stage first (overlaps with compute below)
        const int nx = it + STAGES - 1;
        if (nx < NIT) issue_loads(smem_base, a_gbase, b_gbase, nx, tid);
        asm volatile("cp.async.commit_group;" ::: "memory");

        const int s = it & (STAGES - 1);
        const uint32_t a_base = smem_base + (uint32_t)s * STAGE_BYTES;
        const uint32_t b_base = a_base + A_STAGE_BYTES;

#pragma unroll
        for (int ks = 0; ks < 4; ks++) {
            uint32_t afr[4][4];
            uint32_t bfr[8][2];
            // A fragments: one ldmatrix.x4 per 16-row slab
#pragma unroll
            for (int mi = 0; mi < 4; mi++) {
                uint32_t c8 = (uint32_t)(((ks << 1) | a_hi) ^ xk);
                uint32_t addr = a_base + (uint32_t)(a_row_l + mi * 16) * 128u + (c8 << 4);
                ldsm_x4(afr[mi], addr);
            }
            // B fragments: one ldmatrix.x4 per n16 pair -> (ni=2p, ni=2p+1)
#pragma unroll
            for (int p = 0; p < 4; p++) {
                uint32_t c8 = (uint32_t)(((ks << 1) | b_lo) ^ xk);
                uint32_t addr = b_base + (uint32_t)(b_row_l + p * 16) * 128u + (c8 << 4);
                uint32_t r[4];
                ldsm_x4(r, addr);
                bfr[2 * p][0] = r[0]; bfr[2 * p][1] = r[1];
                bfr[2 * p + 1][0] = r[2]; bfr[2 * p + 1][1] = r[3];
            }
#pragma unroll
            for (int mi = 0; mi < 4; mi++)
#pragma unroll
                for (int ni = 0; ni < 8; ni++)
                    mma_m16n8k16(acc[mi][ni], afr[mi], bfr[ni]);
        }
    }

    asm volatile("cp.async.wait_group 0;" ::: "memory");

    // epilogue: GELU + direct float2 stores
    const int grow0 = mt * TILE_M + warp_m * 64 + lane4;
    const int gcol0 = nt * TILE_N + warp_n * 64 + 2 * lanem;
#pragma unroll
    for (int mi = 0; mi < 4; mi++) {
#pragma unroll
        for (int ni = 0; ni < 8; ni++) {
            int r = grow0 + mi * 16;
            int c = gcol0 + ni * 8;
            float2 v0, v1;
            v0.x = gelu_exact(acc[mi][ni][0]);
            v0.y = gelu_exact(acc[mi][ni][1]);
            v1.x = gelu_exact(acc[mi][ni][2]);
            v1.y = gelu_exact(acc[mi][ni][3]);
            *reinterpret_cast<float2*>(out + (size_t)r * DDIM + c) = v0;
            *reinterpret_cast<float2*>(out + (size_t)(r + 8) * DDIM + c) = v1;
        }
    }
}

// ---------------- launch ----------------
extern "C" void kernel_launch(void* const* d_in, const int* in_sizes, int n_in,
                              void* d_out, int out_size) {
    const float* x  = (const float*)d_in[0];
    const float* bw = (const float*)d_in[1];
    const float* sw = (const float*)d_in[2];
    const float* ss = (const float*)d_in[3];
    float* out = (float*)d_out;

    cudaFuncSetAttribute(gemm_kernel, cudaFuncAttributeMaxDynamicSharedMemorySize, DYN_SMEM);

    prep_act_kernel<<<(NTOK * HDIM) / 256, 256>>>(x);
    prep_w_kernel<<<(DDIM * HDIM) / 256, 256>>>(bw, sw, ss);
    gemm_kernel<<<MT * NT, GTHREADS, DYN_SMEM>>>(out);
}

// round 8
// speedup vs baseline: 2.4931x; 1.1105x over previous
#include <cuda_runtime.h>
#include <cuda_fp16.h>
#include <cstdint>
#include <cstddef>

// ---------------- problem dims (fixed) ----------------
#define NTOK 8192            // 4*2048 tokens
#define HDIM 1024
#define DDIM 4096
#define KDIM 9216            // HDIM * 9 (silu block [0,1024) + bases block [1024,9216))

// ---------------- GEMM tiling ----------------
#define TILE_M 128
#define TILE_N 128
#define KCHUNK 64            // fp16 elems per k-iter = 128 bytes per row
#define STAGES 3
#define NIT (KDIM / KCHUNK)  // 144
#define GTHREADS 256         // 8 warps: 2 (M) x 4 (N), warp tile 64x32
#define MT (NTOK / TILE_M)   // 64
#define NT (DDIM / TILE_N)   // 32

#define A_STAGE_BYTES (TILE_M * 128)   // 16384
#define B_STAGE_BYTES (TILE_N * 128)   // 16384
#define STAGE_BYTES (A_STAGE_BYTES + B_STAGE_BYTES)
#define DYN_SMEM (STAGES * STAGE_BYTES + 1024)   // ~97 KB -> 2 CTAs/SM

// ---------------- scratch (allocation-free: __device__ globals) ----------------
__device__ __half g_act[(size_t)NTOK * KDIM];   // 151 MB fp16 features
__device__ __half g_w[(size_t)DDIM * KDIM];     // 75.5 MB fp16 fused weights

// ---------------- helpers ----------------
__device__ __forceinline__ void cp_async16(uint32_t dst, const void* src) {
    asm volatile("cp.async.cg.shared.global [%0], [%1], 16;"
                 :: "r"(dst), "l"(src) : "memory");
}

__device__ __forceinline__ float gelu_exact(float v) {
    return 0.5f * v * (1.0f + erff(v * 0.70710678118654752f));
}

// knot value: matches numpy float32 arange(i-3)*0.4f + (-1.0f) — constant-folded
__device__ __forceinline__ float knot(int t) {
    return __fadd_rn(__fmul_rn(0.4f, (float)(t - 3)), -1.0f);
}

__device__ __forceinline__ void ldsm_x4(uint32_t* r, uint32_t addr) {
    asm volatile("ldmatrix.sync.aligned.m8n8.x4.shared.b16 {%0,%1,%2,%3}, [%4];"
                 : "=r"(r[0]), "=r"(r[1]), "=r"(r[2]), "=r"(r[3]) : "r"(addr));
}

__device__ __forceinline__ void mma_m16n8k16(float* c, const uint32_t* a, const uint32_t* b) {
    asm volatile(
        "mma.sync.aligned.m16n8k16.row.col.f32.f16.f16.f32 "
        "{%0,%1,%2,%3}, {%4,%5,%6,%7}, {%8,%9}, {%0,%1,%2,%3};"
        : "+f"(c[0]), "+f"(c[1]), "+f"(c[2]), "+f"(c[3])
        : "r"(a[0]), "r"(a[1]), "r"(a[2]), "r"(a[3]), "r"(b[0]), "r"(b[1]));
}

// pack 8 floats -> uint4 of fp16
__device__ __forceinline__ uint4 pack8_h(const float* v) {
    union { __half2 h2[4]; uint4 u; } u;
    u.h2[0] = __floats2half2_rn(v[0], v[1]);
    u.h2[1] = __floats2half2_rn(v[2], v[3]);
    u.h2[2] = __floats2half2_rn(v[4], v[5]);
    u.h2[3] = __floats2half2_rn(v[6], v[7]);
    return u.u;
}

// ---------------- merged prep kernel ----------------
#define ACT_BLOCKS ((NTOK * HDIM) / 256)
#define W_BLOCKS ((DDIM * HDIM) / 256)

__global__ void __launch_bounds__(256) prep_kernel(const float* __restrict__ x,
                                                   const float* __restrict__ bw,
                                                   const float* __restrict__ sw,
                                                   const float* __restrict__ ss) {
    if (blockIdx.x < ACT_BLOCKS) {
        int idx = blockIdx.x * 256 + threadIdx.x;
        float xv = x[idx];
        float sig = 1.0f / (1.0f + __expf(-xv));
        float silu = xv * sig;

        float b[11];
#pragma unroll
        for (int t = 0; t < 11; t++)
            b[t] = (xv >= knot(t) && xv < knot(t + 1)) ? 1.0f : 0.0f;
#pragma unroll
        for (int k = 1; k <= 3; k++) {
#pragma unroll
            for (int t = 0; t + k < 11; t++) {
                float rl = 1.0f / (knot(t + k) - knot(t));
                float rr = 1.0f / (knot(t + k + 1) - knot(t + 1));
                float left = (xv - knot(t)) * rl;
                float right = (knot(t + k + 1) - xv) * rr;
                b[t] = left * b[t] + right * b[t + 1];
            }
        }

        int n = idx >> 10;
        int h = idx & 1023;
        size_t base = (size_t)n * KDIM;
        g_act[base + h] = __float2half_rn(silu);
        *reinterpret_cast<uint4*>(&g_act[base + 1024 + 8 * (size_t)h]) = pack8_h(b);
    } else {
        int idx = (blockIdx.x - ACT_BLOCKS) * 256 + threadIdx.x;
        float base = bw[idx];
        float scal = ss[idx];
        int d = idx >> 10;
        int h = idx & 1023;

        float w[8];
        const float4* swp = reinterpret_cast<const float4*>(sw + (size_t)idx * 8);
        float4 s0 = swp[0], s1 = swp[1];
        w[0] = s0.x * scal; w[1] = s0.y * scal; w[2] = s0.z * scal; w[3] = s0.w * scal;
        w[4] = s1.x * scal; w[5] = s1.y * scal; w[6] = s1.z * scal; w[7] = s1.w * scal;

        size_t dbase = (size_t)d * KDIM;
        g_w[dbase + h] = __float2half_rn(base);
        *reinterpret_cast<uint4*>(&g_w[dbase + 1024 + 8 * (size_t)h]) = pack8_h(w);
    }
}

// ---------------- GEMM: issue cp.async for k-iter `it` into stage `s` ----------------
__device__ __forceinline__ void issue_loads(uint32_t smem_base,
                                            const char* a_gbase, const char* b_gbase,
                                            int it, int s, int tid) {
    uint32_t a_s = smem_base + (uint32_t)s * STAGE_BYTES;
    uint32_t b_s = a_s + A_STAGE_BYTES;
    const char* a_g = a_gbase + (size_t)it * 128;   // 64 halfs = 128 B per k-iter
    const char* b_g = b_gbase + (size_t)it * 128;

    // A tile: 128 rows x 128B = 1024 x 16B  (4 per thread)
#pragma unroll
    for (int i = 0; i < 4; i++) {
        int c = tid + i * GTHREADS;
        int row = c >> 3, c8 = c & 7;
        uint32_t off = ((uint32_t)row << 7) | ((uint32_t)c8 << 4);
        uint32_t swz = off ^ ((off >> 3) & 0x70u);
        cp_async16(a_s + swz, a_g + (size_t)row * (KDIM * 2) + ((size_t)c8 << 4));
    }
    // B tile: 128 rows x 128B = 1024 x 16B  (4 per thread)
#pragma unroll
    for (int i = 0; i < 4; i++) {
        int c = tid + i * GTHREADS;
        int row = c >> 3, c8 = c & 7;
        uint32_t off = ((uint32_t)row << 7) | ((uint32_t)c8 << 4);
        uint32_t swz = off ^ ((off >> 3) & 0x70u);
        cp_async16(b_s + swz, b_g + (size_t)row * (KDIM * 2) + ((size_t)c8 << 4));
    }
}

// ---------------- GEMM kernel (2 CTAs/SM) ----------------
__global__ void __launch_bounds__(GTHREADS, 2) gemm_kernel(float* __restrict__ out) {
    extern __shared__ char dsmem[];

    const int tid = threadIdx.x;
    const int wid = tid >> 5;
    const int lane = tid & 31;
    const int lane4 = lane >> 2;   // groupID 0..7
    const int lanem = lane & 3;    // threadID-in-group 0..3
    const int warp_m = wid & 1;    // 0..1  (64-row slabs)
    const int warp_n = wid >> 1;   // 0..3  (32-col slabs)

    // grouped rasterization: 16 m-tiles x 16 n-tiles per group (256 CTAs)
    const int bid = blockIdx.x;
    const int g = bid >> 8;
    const int r = bid & 255;
    const int mt = ((g & 3) << 4) | (r & 15);
    const int nt = ((g >> 2) << 4) | (r >> 4);

    uint32_t smem_raw = (uint32_t)__cvta_generic_to_shared(dsmem);
    uint32_t smem_base = (smem_raw + 1023u) & ~1023u;

    const char* a_gbase = (const char*)(g_act + (size_t)mt * TILE_M * KDIM);
    const char* b_gbase = (const char*)(g_w + (size_t)nt * TILE_N * KDIM);

    float acc[4][4][4];
#pragma unroll
    for (int mi = 0; mi < 4; mi++)
#pragma unroll
        for (int ni = 0; ni < 4; ni++)
#pragma unroll
            for (int j = 0; j < 4; j++) acc[mi][ni][j] = 0.0f;

    // prologue: fill STAGES-1 stages
#pragma unroll
    for (int it = 0; it < STAGES - 1; it++) {
        issue_loads(smem_base, a_gbase, b_gbase, it, it, tid);
        asm volatile("cp.async.commit_group;" ::: "memory");
    }

    // ldmatrix lane-address components
    const int xk = lane & 7;                     // swizzle XOR term (= row & 7)
    const int a_row_l = warp_m * 64 + (lane & 15);
    const int a_hi = lane >> 4;
    const int quad = lane >> 3;
    const int b_row_l = warp_n * 32 + ((quad >> 1) << 3) + (lane & 7);
    const int b_lo = quad & 1;

    int cs = 0;                      // compute-stage cursor
    int ls = STAGES - 1;             // load-stage cursor
    for (int it = 0; it < NIT; it++) {
        asm volatile("cp.async.wait_group 1;" ::: "memory");
        __syncthreads();

        // issue next stage first (overlaps with compute below)
        const int nx = it + STAGES - 1;
        if (nx < NIT) issue_loads(smem_base, a_gbase, b_gbase, nx, ls, tid);
        if (++ls == STAGES) ls = 0;
        asm volatile("cp.async.commit_group;" ::: "memory");

        const uint32_t a_base = smem_base + (uint32_t)cs * STAGE_BYTES;
        const uint32_t b_base = a_base + A_STAGE_BYTES;
        if (++cs == STAGES) cs = 0;

#pragma unroll
        for (int ks = 0; ks < 4; ks++) {
            uint32_t afr[4][4];
            uint32_t bfr[4][2];
            // A fragments: one ldmatrix.x4 per 16-row slab
#pragma unroll
            for (int mi = 0; mi < 4; mi++) {
                uint32_t c8 = (uint32_t)(((ks << 1) | a_hi) ^ xk);
                uint32_t addr = a_base + (uint32_t)(a_row_l + mi * 16) * 128u + (c8 << 4);
                ldsm_x4(afr[mi], addr);
            }
            // B fragments: one ldmatrix.x4 per n16 pair -> (ni=2p, ni=2p+1)
#pragma unroll
            for (int p = 0; p < 2; p++) {
                uint32_t c8 = (uint32_t)(((ks << 1) | b_lo) ^ xk);
                uint32_t addr = b_base + (uint32_t)(b_row_l + p * 16) * 128u + (c8 << 4);
                uint32_t rr[4];
                ldsm_x4(rr, addr);
                bfr[2 * p][0] = rr[0]; bfr[2 * p][1] = rr[1];
                bfr[2 * p + 1][0] = rr[2]; bfr[2 * p + 1][1] = rr[3];
            }
#pragma unroll
            for (int mi = 0; mi < 4; mi++)
#pragma unroll
                for (int ni = 0; ni < 4; ni++)
                    mma_m16n8k16(acc[mi][ni], afr[mi], bfr[ni]);
        }
    }

    asm volatile("cp.async.wait_group 0;" ::: "memory");

    // epilogue: GELU + direct float2 stores
    const int grow0 = mt * TILE_M + warp_m * 64 + lane4;
    const int gcol0 = nt * TILE_N + warp_n * 32 + 2 * lanem;
#pragma unroll
    for (int mi = 0; mi < 4; mi++) {
#pragma unroll
        for (int ni = 0; ni < 4; ni++) {
            int rr = grow0 + mi * 16;
            int c = gcol0 + ni * 8;
            float2 v0, v1;
            v0.x = gelu_exact(acc[mi][ni][0]);
            v0.y = gelu_exact(acc[mi][ni][1]);
            v1.x = gelu_exact(acc[mi][ni][2]);
            v1.y = gelu_exact(acc[mi][ni][3]);
            *reinterpret_cast<float2*>(out + (size_t)rr * DDIM + c) = v0;
            *reinterpret_cast<float2*>(out + (size_t)(rr + 8) * DDIM + c) = v1;
        }
    }
}

// ---------------- launch ----------------
extern "C" void kernel_launch(void* const* d_in, const int* in_sizes, int n_in,
                              void* d_out, int out_size) {
    const float* x  = (const float*)d_in[0];
    const float* bw = (const float*)d_in[1];
    const float* sw = (const float*)d_in[2];
    const float* ss = (const float*)d_in[3];
    float* out = (float*)d_out;

    cudaFuncSetAttribute(gemm_kernel, cudaFuncAttributeMaxDynamicSharedMemorySize, DYN_SMEM);

    prep_kernel<<<ACT_BLOCKS + W_BLOCKS, 256>>>(x, bw, sw, ss);
    gemm_kernel<<<MT * NT, GTHREADS, DYN_SMEM>>>(out);
}